// round 9
// baseline (speedup 1.0000x reference)
#include <cuda_runtime.h>
#include <cstdint>

// ---------------------------------------------------------------------------
// BatchTopK via exact threshold selection on float bit patterns.
//   k_init:    zero hists + scalars.
//   k_main:    R6-proven streaming pass (77.5us @ 79% DRAM): read x, write
//              out=0, detect >= 3.0 (max-tree + branch), candidates ->
//              global per-warp slabs (smem counter), raw counts stored.
//   k_hist:    coalesced predicated walk of all slab slots -> 16384-bin hist.
//   k_scan:    single block suffix-scans hist -> B*, c_above, k_total.
//   k_scatter: coalesced walk: scatter bin>B* winners, boundary bin -> buf.
//   k_refine:  single block, parallel refinement of exact threshold bits +
//              ties by smallest index (lax.top_k tie-break); guarded exact
//              full fallback for any distribution/overflow (no-op normally).
// No __threadfence / tickets; cross-kernel visibility via launch ordering.
// ---------------------------------------------------------------------------

#define T_DET      3.0f
#define NBINS      16384
#define SLAB       32
#define NUM_WARPS  65536
#define BND_CAP    (1u << 20)
#define TIE_CAP    4096

__device__ unsigned g_hist[NBINS];
__device__ unsigned g_hist2[NBINS];
__device__ int      g_B_star;
__device__ unsigned g_c_above;
__device__ unsigned g_k_total;
__device__ int      g_need_full;
__device__ int      g_ovf;
__device__ unsigned g_nb;
__device__ unsigned g_warp_cnt[NUM_WARPS];
__device__ uint2    g_cand[(size_t)NUM_WARPS * SLAB];
__device__ unsigned g_bnd_bits[BND_CAP];
__device__ unsigned g_bnd_idx[BND_CAP];

__global__ void k_init() {
    int i = blockIdx.x * blockDim.x + threadIdx.x;
    int stride = gridDim.x * blockDim.x;
    for (int b = i; b < NBINS; b += stride) { g_hist[b] = 0u; g_hist2[b] = 0u; }
    if (i == 0) { g_nb = 0u; g_ovf = 0; }
}

__device__ __forceinline__ void handle4(float4 a, int i4, unsigned* wctr, uint2* slab) {
    float vals[4] = {a.x, a.y, a.z, a.w};
#pragma unroll
    for (int j = 0; j < 4; j++) {
        if (vals[j] >= T_DET) {
            unsigned pos = atomicAdd(wctr, 1u);
            if (pos < SLAB) slab[pos] = make_uint2(__float_as_uint(vals[j]),
                                                   (unsigned)(4 * i4 + j));
        }
    }
}

// R6-proven streaming pass: zero out + per-warp global-slab compaction.
__global__ void __launch_bounds__(1024, 1)
k_main(const float4* __restrict__ x4, float4* __restrict__ o4, int n4, int ntiles) {
    __shared__ unsigned wcnt[32];
    if (threadIdx.x < 32) wcnt[threadIdx.x] = 0u;
    __syncthreads();

    const int lane   = threadIdx.x & 31;
    const int wlocal = threadIdx.x >> 5;
    const int W      = blockIdx.x * 32 + wlocal;
    const int NW     = gridDim.x * 32;
    uint2*    slab   = g_cand + (size_t)W * SLAB;
    unsigned* wctr   = &wcnt[wlocal];
    const float4 z4  = make_float4(0.f, 0.f, 0.f, 0.f);

    for (int tile = W; tile < ntiles; tile += NW) {
        const int base = tile * 256;              // 256 float4 per tile
        if (base + 256 <= n4) {
            float4 v[8];
#pragma unroll
            for (int it = 0; it < 8; it++) v[it] = x4[base + it * 32 + lane];
#pragma unroll
            for (int it = 0; it < 8; it++) o4[base + it * 32 + lane] = z4;
#pragma unroll
            for (int p = 0; p < 4; p++) {
                float4 a = v[2 * p], b = v[2 * p + 1];
                float m = fmaxf(fmaxf(fmaxf(a.x, a.y), fmaxf(a.z, a.w)),
                                fmaxf(fmaxf(b.x, b.y), fmaxf(b.z, b.w)));
                if (m >= T_DET) {
                    handle4(a, base + (2 * p) * 32 + lane, wctr, slab);
                    handle4(b, base + (2 * p + 1) * 32 + lane, wctr, slab);
                }
            }
        } else {
            for (int it = 0; it < 8; it++) {
                int i4 = base + it * 32 + lane;
                if (i4 < n4) {
                    float4 a = x4[i4];
                    o4[i4] = z4;
                    handle4(a, i4, wctr, slab);
                }
            }
        }
    }
    __syncwarp();
    if (lane == 0) g_warp_cnt[W] = wcnt[wlocal];   // raw count (uncapped)
}

// Coalesced predicated walk of all slab slots -> histogram.
__global__ void __launch_bounds__(1024, 1)
k_hist(int nwarps) {
    long long nslots = (long long)nwarps * SLAB;
    long long stride = (long long)gridDim.x * blockDim.x;
    for (long long s = blockIdx.x * (long long)blockDim.x + threadIdx.x;
         s < nslots; s += stride) {
        int w = (int)(s >> 5);           // SLAB == 32
        int e = (int)(s & 31);
        unsigned cnt = g_warp_cnt[w];    // broadcast within warp
        if (e == 0 && cnt > SLAB) g_ovf = 1;
        if ((unsigned)e < min(cnt, (unsigned)SLAB))
            atomicAdd(&g_hist[g_cand[s].x >> 17], 1u);
    }
}

// Single block: suffix scan -> threshold bin.
__global__ void __launch_bounds__(1024, 1)
k_scan(const int* __restrict__ kptr, int n) {
    __shared__ unsigned s_arr[1024];
    __shared__ int s_found;
    __shared__ unsigned sK;
    int t = threadIdx.x;
    if (t == 0) {
        s_found = 0;
        unsigned batch = (unsigned)(n >> 16);   // d_sae = 65536
        g_k_total = (unsigned)(*kptr) * batch;
        sK = g_k_total;
    }
    __syncthreads();
    unsigned K = sK;
    const int C = NBINS / 1024;
    unsigned h[C];
    unsigned a = 0;
#pragma unroll
    for (int jj = 0; jj < C; jj++) { h[jj] = __ldcg(&g_hist[t * C + jj]); a += h[jj]; }
    s_arr[t] = a;
    __syncthreads();
    for (int off = 1; off < 1024; off <<= 1) {
        unsigned v = (t + off < 1024) ? s_arr[t + off] : 0u;
        __syncthreads();
        s_arr[t] += v;
        __syncthreads();
    }
    unsigned running = s_arr[t] - a;
#pragma unroll
    for (int jj = C - 1; jj >= 0; --jj) {
        if (running < K && running + h[jj] >= K) {
            g_B_star = t * C + jj;
            g_c_above = running;
            s_found = 1;
        }
        running += h[jj];
    }
    __syncthreads();
    if (t == 0) g_need_full = (!s_found || __ldcg((const int*)&g_ovf)) ? 1 : 0;
}

// Coalesced walk: scatter winners, boundary -> buffer.
__global__ void __launch_bounds__(1024, 1)
k_scatter(float* __restrict__ out, int nwarps) {
    if (g_need_full) return;
    const int B = g_B_star;
    long long nslots = (long long)nwarps * SLAB;
    long long stride = (long long)gridDim.x * blockDim.x;
    for (long long s = blockIdx.x * (long long)blockDim.x + threadIdx.x;
         s < nslots; s += stride) {
        int w = (int)(s >> 5);
        int e = (int)(s & 31);
        unsigned cnt = min(g_warp_cnt[w], (unsigned)SLAB);
        if ((unsigned)e < cnt) {
            uint2 c = g_cand[s];
            int bin = (int)(c.x >> 17);
            if (bin > B) {
                out[c.y] = __uint_as_float(c.x);
            } else if (bin == B) {
                unsigned p = atomicAdd(&g_nb, 1u);
                if (p < BND_CAP) { g_bnd_bits[p] = c.x; g_bnd_idx[p] = c.y; }
            }
        }
    }
}

// Parallel crossing-finder over NB bins held in s_h (suffix-sum in s_arr).
// Sets *o_bin / *o_above for the unique bin where the suffix sum crosses m.
__device__ void find_cross(unsigned* s_h, unsigned* s_arr, int NB, unsigned m,
                           int* o_bin, unsigned* o_above) {
    int t = threadIdx.x;
    if (t < NB) s_arr[t] = s_h[t];
    __syncthreads();
    for (int off = 1; off < NB; off <<= 1) {
        unsigned v = (t < NB && t + off < NB) ? s_arr[t + off] : 0u;
        __syncthreads();
        if (t < NB) s_arr[t] += v;
        __syncthreads();
    }
    if (t < NB) {
        unsigned incl = s_arr[t];
        unsigned above = incl - s_h[t];
        if (above < m && incl >= m) { *o_bin = t; *o_above = above; }
    }
    __syncthreads();
}

// Block-wide refine+tie logic over the boundary buffer (parallel scans).
__device__ void sel2_body(float* __restrict__ out) {
    __shared__ unsigned h1[512];
    __shared__ unsigned h2[256];
    __shared__ unsigned s_arr[512];
    __shared__ unsigned tie_idx[TIE_CAP];
    __shared__ unsigned s_tcnt;
    __shared__ int s_s1;
    __shared__ unsigned s_c1;
    __shared__ int s_b2;
    __shared__ unsigned s_c2;
    __shared__ unsigned s_Tbits;
    __shared__ unsigned s_r;
    __shared__ int s_mode;

    int t = threadIdx.x;
    unsigned nb = min(g_nb, (unsigned)BND_CAP);
    int B = g_B_star;
    unsigned K = g_k_total, ca = g_c_above;

    if (t == 0) {
        if (nb == 0u || ca >= K) s_mode = 2;
        else s_mode = ((K - ca) >= nb) ? 1 : 0;
    }
    __syncthreads();
    if (s_mode == 2) return;
    if (s_mode == 1) {
        for (unsigned i = t; i < nb; i += blockDim.x)
            out[g_bnd_idx[i]] = __uint_as_float(g_bnd_bits[i]);
        return;
    }
    unsigned m = K - ca;

    // level-1: bits[16:8]
    if (t < 512) h1[t] = 0u;
    __syncthreads();
    for (unsigned i = t; i < nb; i += blockDim.x)
        atomicAdd(&h1[(g_bnd_bits[i] >> 8) & 0x1FFu], 1u);
    __syncthreads();
    find_cross(h1, s_arr, 512, m, &s_s1, &s_c1);
    int s1 = s_s1; unsigned c1 = s_c1;

    // level-2: bits[7:0] within sub-bin s1
    if (t < 256) h2[t] = 0u;
    __syncthreads();
    for (unsigned i = t; i < nb; i += blockDim.x) {
        unsigned bits = g_bnd_bits[i];
        if (((bits >> 8) & 0x1FFu) == (unsigned)s1)
            atomicAdd(&h2[bits & 0xFFu], 1u);
    }
    __syncthreads();
    find_cross(h2, s_arr, 256, m - c1, &s_b2, &s_c2);
    if (t == 0) {
        s_Tbits = ((unsigned)B << 17) | ((unsigned)s1 << 8) | (unsigned)s_b2;
        s_r = (m - c1) - s_c2;
        s_tcnt = 0u;
    }
    __syncthreads();
    unsigned Tb = s_Tbits, r = s_r;

    for (unsigned i = t; i < nb; i += blockDim.x) {
        unsigned bits = g_bnd_bits[i];
        if (bits > Tb) {
            out[g_bnd_idx[i]] = __uint_as_float(bits);
        } else if (bits == Tb) {
            unsigned p = atomicAdd(&s_tcnt, 1u);
            if (p < TIE_CAP) tie_idx[p] = g_bnd_idx[i];
        }
    }
    __syncthreads();
    unsigned tcnt = min(s_tcnt, (unsigned)TIE_CAP);
    if (r >= tcnt) {
        for (unsigned i = t; i < tcnt; i += blockDim.x)
            out[tie_idx[i]] = __uint_as_float(Tb);
        return;
    }
    // rare: pick r smallest indices among ties (stable tie-break)
    for (unsigned i = t; i < TIE_CAP; i += blockDim.x)
        if (i >= tcnt) tie_idx[i] = 0xFFFFFFFFu;
    __syncthreads();
    for (unsigned kk = 2; kk <= TIE_CAP; kk <<= 1) {
        for (unsigned j = kk >> 1; j > 0; j >>= 1) {
            for (unsigned i = t; i < TIE_CAP; i += blockDim.x) {
                unsigned ixj = i ^ j;
                if (ixj > i) {
                    unsigned va = tie_idx[i], vb = tie_idx[ixj];
                    bool asc = ((i & kk) == 0);
                    if ((va > vb) == asc) { tie_idx[i] = vb; tie_idx[ixj] = va; }
                }
            }
            __syncthreads();
        }
    }
    for (unsigned i = t; i < r; i += blockDim.x)
        out[tie_idx[i]] = __uint_as_float(Tb);
}

// Single block: boundary refinement; guarded exact fallback.
__global__ void __launch_bounds__(1024, 1)
k_refine(const float4* __restrict__ x4, float* __restrict__ out, int n4) {
    if (g_need_full) {
        int t = threadIdx.x;
        unsigned K = g_k_total;
        if (K == 0u) return;   // out already zeroed

        for (int i = t; i < n4; i += 1024) {
            float4 v = x4[i];
            float vals[4] = {v.x, v.y, v.z, v.w};
#pragma unroll
            for (int j = 0; j < 4; j++)
                if (vals[j] > 0.0f)
                    atomicAdd(&g_hist2[__float_as_uint(vals[j]) >> 17], 1u);
        }
        __syncthreads();

        __shared__ unsigned s_arr[1024];
        __shared__ int s_found;
        const int C = NBINS / 1024;
        unsigned h[C];
        unsigned a = 0;
        if (t == 0) s_found = 0;
        __syncthreads();
#pragma unroll
        for (int jj = 0; jj < C; jj++) { h[jj] = g_hist2[t * C + jj]; a += h[jj]; }
        s_arr[t] = a;
        __syncthreads();
        for (int off = 1; off < 1024; off <<= 1) {
            unsigned v = (t + off < 1024) ? s_arr[t + off] : 0u;
            __syncthreads();
            s_arr[t] += v;
            __syncthreads();
        }
        unsigned running = s_arr[t] - a;
#pragma unroll
        for (int jj = C - 1; jj >= 0; --jj) {
            if (running < K && running + h[jj] >= K) {
                g_B_star = t * C + jj;
                g_c_above = running;
                s_found = 1;
            }
            running += h[jj];
        }
        __syncthreads();
        if (t == 0 && !s_found) { g_B_star = -1; g_c_above = s_arr[0]; }
        __syncthreads();

        int B = g_B_star;
        for (int i = t; i < n4; i += 1024) {
            float4 v = x4[i];
            float vals[4] = {v.x, v.y, v.z, v.w};
#pragma unroll
            for (int j = 0; j < 4; j++) {
                float val = vals[j];
                if (val > 0.0f) {
                    unsigned u = __float_as_uint(val);
                    int bin = (int)(u >> 17);
                    if (bin > B) {
                        out[4 * i + j] = val;
                    } else if (bin == B) {
                        unsigned p = atomicAdd(&g_nb, 1u);
                        if (p < BND_CAP) { g_bnd_bits[p] = u; g_bnd_idx[p] = (unsigned)(4 * i + j); }
                    }
                }
            }
        }
        __syncthreads();
        sel2_body(out);
        return;
    }
    sel2_body(out);
}

extern "C" void kernel_launch(void* const* d_in, const int* in_sizes, int n_in,
                              void* d_out, int out_size) {
    const float* x    = (const float*)d_in[0];
    const int*   kptr = (const int*)d_in[1];
    float*       out  = (float*)d_out;
    int n  = in_sizes[0];
    int n4 = n >> 2;

    int ntiles = (n4 + 255) / 256;
    int main_blocks = (ntiles + 31) / 32;
    if (main_blocks > NUM_WARPS / 32) main_blocks = NUM_WARPS / 32;
    int nwarps = main_blocks * 32;

    k_init<<<32, 1024>>>();
    k_main<<<main_blocks, 1024>>>((const float4*)x, (float4*)out, n4, ntiles);
    k_hist<<<128, 1024>>>(nwarps);
    k_scan<<<1, 1024>>>(kptr, n);
    k_scatter<<<128, 1024>>>(out, nwarps);
    k_refine<<<1, 1024>>>((const float4*)x, out, n4);
}